// round 1
// baseline (speedup 1.0000x reference)
#include <cuda_runtime.h>

// Scalar accumulator in device global memory (no allocations allowed).
__device__ double g_sum;

struct V3 { float x, y, z; };

__device__ __forceinline__ V3 vsub(V3 a, V3 b) { return {a.x - b.x, a.y - b.y, a.z - b.z}; }
__device__ __forceinline__ float vdot(V3 a, V3 b) { return a.x * b.x + a.y * b.y + a.z * b.z; }
__device__ __forceinline__ V3 vcross(V3 a, V3 b) {
    return {a.y * b.z - a.z * b.y,
            a.z * b.x - a.x * b.z,
            a.x * b.y - a.y * b.x};
}
// Branchless select of one of three vectors by index k in {0,1,2}.
__device__ __forceinline__ V3 vsel(V3 a0, V3 a1, V3 a2, int k) {
    V3 r;
    r.x = (k == 0) ? a0.x : ((k == 1) ? a1.x : a2.x);
    r.y = (k == 0) ? a0.y : ((k == 1) ? a1.y : a2.y);
    r.z = (k == 0) ? a0.z : ((k == 1) ? a1.z : a2.z);
    return r;
}

__global__ void k_init() { g_sum = 0.0; }

__global__ __launch_bounds__(256)
void k_edge(const float* __restrict__ tp,     // (F,3,3)
            const float* __restrict__ rot,    // (F,3,3)
            const float* __restrict__ verts,  // (V,3)
            const int*   __restrict__ faces,  // (3,F)  (faces.T stored row-major)
            const int*   __restrict__ edges,  // (E,2)
            const int*   __restrict__ fids,   // (E,2)
            int F, int E)
{
    int e = blockIdx.x * blockDim.x + threadIdx.x;
    double val = 0.0;

    if (e < E) {
        int a  = edges[2 * e + 0];
        int b  = edges[2 * e + 1];
        int f1 = fids[2 * e + 0];
        int f2 = fids[2 * e + 1];

        // Face vertex index triples: Ft[f,k] = faces[k*F + f]
        int fa0 = faces[f1], fa1 = faces[F + f1], fa2 = faces[2 * F + f1];
        int fb0 = faces[f2], fb1 = faces[F + f2], fb2 = faces[2 * F + f2];

        // position of edge vertices within each face (JAX -1 wraps to 2)
        int pA1 = (fa0 == a) ? 0 : ((fa1 == a) ? 1 : 2);
        int pB1 = (fa0 == b) ? 0 : ((fa1 == b) ? 1 : 2);
        int pA2 = (fb0 == a) ? 0 : ((fb1 == a) ? 1 : 2);
        int pB2 = (fb0 == b) ? 0 : ((fb1 == b) ? 1 : 2);

        // Load transformed_prism rows for both faces
        const float* q1 = tp + (size_t)f1 * 9;
        const float* q2 = tp + (size_t)f2 * 9;
        V3 t1_0 = {q1[0], q1[1], q1[2]};
        V3 t1_1 = {q1[3], q1[4], q1[5]};
        V3 t1_2 = {q1[6], q1[7], q1[8]};
        V3 t2_0 = {q2[0], q2[1], q2[2]};
        V3 t2_1 = {q2[3], q2[4], q2[5]};
        V3 t2_2 = {q2[6], q2[7], q2[8]};

        // Face normals from tp: normalize(cross(t0-t1, t0-t2))
        V3 n1c = vcross(vsub(t1_0, t1_1), vsub(t1_0, t1_2));
        V3 n2c = vcross(vsub(t2_0, t2_1), vsub(t2_0, t2_2));
        float in1 = rsqrtf(vdot(n1c, n1c));
        float in2 = rsqrtf(vdot(n2c, n2c));
        V3 n1 = {n1c.x * in1, n1c.y * in1, n1c.z * in1};
        V3 n2 = {n2c.x * in2, n2c.y * in2, n2c.z * in2};

        // dr = r1 - r2 ;  x = n1 @ dr, y = n2 @ dr  (row-vector times matrix)
        const float* R1 = rot + (size_t)f1 * 9;
        const float* R2 = rot + (size_t)f2 * 9;
        float dr[9];
        #pragma unroll
        for (int i = 0; i < 9; i++) dr[i] = R1[i] - R2[i];

        V3 x = {n1.x * dr[0] + n1.y * dr[3] + n1.z * dr[6],
                n1.x * dr[1] + n1.y * dr[4] + n1.z * dr[7],
                n1.x * dr[2] + n1.y * dr[5] + n1.z * dr[8]};
        V3 y = {n2.x * dr[0] + n2.y * dr[3] + n2.z * dr[6],
                n2.x * dr[1] + n2.y * dr[4] + n2.z * dr[7],
                n2.x * dr[2] + n2.y * dr[5] + n2.z * dr[8]};

        // u = tp[f1, pA1] - tp[f2, pA2] ; w = tp[f1, pB1] - tp[f2, pB2]
        V3 u = vsub(vsel(t1_0, t1_1, t1_2, pA1), vsel(t2_0, t2_1, t2_2, pA2));
        V3 w = vsub(vsel(t1_0, t1_1, t1_2, pB1), vsel(t2_0, t2_1, t2_2, pB2));

        // Closed-form of (pair * coeff).sum() / 9
        float energy = (3.0f * vdot(u, u) + 3.0f * vdot(w, w) + 3.0f * vdot(u, w)
                      + vdot(x, x) + vdot(y, y) + vdot(x, y)) * (1.0f / 9.0f);

        // Face areas from mesh verts
        const float* va0 = verts + (size_t)fa0 * 3;
        const float* va1 = verts + (size_t)fa1 * 3;
        const float* va2 = verts + (size_t)fa2 * 3;
        const float* vb0 = verts + (size_t)fb0 * 3;
        const float* vb1 = verts + (size_t)fb1 * 3;
        const float* vb2 = verts + (size_t)fb2 * 3;
        V3 P1_0 = {va0[0], va0[1], va0[2]};
        V3 P1_1 = {va1[0], va1[1], va1[2]};
        V3 P1_2 = {va2[0], va2[1], va2[2]};
        V3 P2_0 = {vb0[0], vb0[1], vb0[2]};
        V3 P2_1 = {vb1[0], vb1[1], vb1[2]};
        V3 P2_2 = {vb2[0], vb2[1], vb2[2]};

        V3 c1 = vcross(vsub(P1_1, P1_0), vsub(P1_2, P1_0));
        V3 c2 = vcross(vsub(P2_1, P2_0), vsub(P2_2, P2_0));
        float area1 = 0.5f * sqrtf(vdot(c1, c1));
        float area2 = 0.5f * sqrtf(vdot(c2, c2));

        // weight = |v[a] - v[b]|^2 / (area1 + area2)
        // v[a] is face-1 vertex at position pA1, v[b] at pB1 (already loaded)
        V3 dv = vsub(vsel(P1_0, P1_1, P1_2, pA1), vsel(P1_0, P1_1, P1_2, pB1));
        float weight = vdot(dv, dv) / (area1 + area2);

        val = (double)(energy * weight);
    }

    // --- block reduction in double, one atomic per block ---
    #pragma unroll
    for (int off = 16; off > 0; off >>= 1)
        val += __shfl_down_sync(0xFFFFFFFFu, val, off);

    __shared__ double sh[8];
    int lane = threadIdx.x & 31;
    int wid  = threadIdx.x >> 5;
    if (lane == 0) sh[wid] = val;
    __syncthreads();
    if (wid == 0) {
        val = (lane < (blockDim.x >> 5)) ? sh[lane] : 0.0;
        #pragma unroll
        for (int off = 4; off > 0; off >>= 1)
            val += __shfl_down_sync(0xFFFFFFFFu, val, off);
        if (lane == 0) atomicAdd(&g_sum, val);
    }
}

__global__ void k_fin(float* __restrict__ out) {
    out[0] = (float)g_sum;   // bs == 1
}

extern "C" void kernel_launch(void* const* d_in, const int* in_sizes, int n_in,
                              void* d_out, int out_size)
{
    const float* tp    = (const float*)d_in[0];   // (F,3,3)
    const float* rot   = (const float*)d_in[1];   // (F,3,3)
    const float* verts = (const float*)d_in[2];   // (1,V,3)
    const int*   faces = (const int*)d_in[3];     // (3,F)
    const int*   edges = (const int*)d_in[4];     // (E,2)
    const int*   fids  = (const int*)d_in[5];     // (E,2)

    int F = in_sizes[0] / 9;
    int E = in_sizes[4] / 2;

    k_init<<<1, 1>>>();
    const int threads = 256;
    int blocks = (E + threads - 1) / threads;
    k_edge<<<blocks, threads>>>(tp, rot, verts, faces, edges, fids, F, E);
    k_fin<<<1, 1>>>((float*)d_out);
}

// round 2
// speedup vs baseline: 1.7887x; 1.7887x over previous
#include <cuda_runtime.h>
#include <math.h>

__device__ double g_sum;

struct V3 { float x, y, z; };

__device__ __forceinline__ V3 ld3(const float* __restrict__ p) { return {p[0], p[1], p[2]}; }
__device__ __forceinline__ V3 vsub(V3 a, V3 b) { return {a.x - b.x, a.y - b.y, a.z - b.z}; }
__device__ __forceinline__ float vdot(V3 a, V3 b) { return a.x * b.x + a.y * b.y + a.z * b.z; }
__device__ __forceinline__ V3 vcross(V3 a, V3 b) {
    return {a.y * b.z - a.z * b.y,
            a.z * b.x - a.x * b.z,
            a.x * b.y - a.y * b.x};
}

// normal of face f from transformed_prism row block: normalize(cross(t0-t1, t0-t2))
__device__ __forceinline__ V3 face_normal(const float* __restrict__ q) {
    V3 t0 = ld3(q), t1 = ld3(q + 3), t2 = ld3(q + 6);
    V3 c = vcross(vsub(t0, t1), vsub(t0, t2));
    float s = rsqrtf(vdot(c, c));
    return {c.x * s, c.y * s, c.z * s};
}

__device__ __forceinline__ float tri_area(V3 p1, V3 p2, V3 p3) {
    V3 c = vcross(vsub(p2, p1), vsub(p3, p1));
    return 0.5f * sqrtf(vdot(c, c));
}

// One edge's contribution.
// u = prism-vertex diff (vertex A), w = (vertex B); na/nb = normals tied to A/B;
// r1/r2 = rotation blocks of the two faces; dv2 = |v[A]-v[B]|^2; asum = area1+area2.
// Closed form of (pair*coeff).sum()/9 = (3|u|^2+3|w|^2+3u.w + |x|^2+|y|^2+x.y)/9
// with x = na @ (r1-r2), y = nb @ (r1-r2).   (fully symmetric in A<->B and f1<->f2)
__device__ __forceinline__ double edge_term(
    V3 u, V3 w, V3 na, V3 nb,
    const float* __restrict__ r1, const float* __restrict__ r2,
    float dv2, float asum)
{
    float dr[9];
    #pragma unroll
    for (int i = 0; i < 9; i++) dr[i] = r1[i] - r2[i];

    V3 x = {na.x * dr[0] + na.y * dr[3] + na.z * dr[6],
            na.x * dr[1] + na.y * dr[4] + na.z * dr[7],
            na.x * dr[2] + na.y * dr[5] + na.z * dr[8]};
    V3 y = {nb.x * dr[0] + nb.y * dr[3] + nb.z * dr[6],
            nb.x * dr[1] + nb.y * dr[4] + nb.z * dr[7],
            nb.x * dr[2] + nb.y * dr[5] + nb.z * dr[8]};

    float en = (3.0f * (vdot(u, u) + vdot(w, w) + vdot(u, w))
              + vdot(x, x) + vdot(y, y) + vdot(x, y)) * (1.0f / 9.0f);
    return (double)(en * (dv2 / asum));
}

__global__ void k_init() { g_sum = 0.0; }

// One thread per grid cell (i,j), i = blockIdx.y, j over x. Each cell owns:
//   diagonal edge   (v10,v01) between tri1(i,j)   and tri2(i,j)        -- always
//   horizontal edge (v10,v11) between tri2(i,j)   and tri1(i+1,j)     -- if i < m-1
//   vertical edge   (v11,v01) between tri2(i,j)   and tri1(i,j+1)     -- if j < m-1
// Face ids: tri1(i,j) = i*m+j ; tri2(i,j) = m*m + i*m+j  (m = n-1).
// NOTE: reference indexes `normals` by VERTEX ids (normals[edges[:,0]]) -- we
// reproduce that exactly: edge-endpoint normals come from tp[vertex_id].
__global__ __launch_bounds__(256)
void k_cell(const float* __restrict__ tp,     // (F,3,3)
            const float* __restrict__ rot,    // (F,3,3)
            const float* __restrict__ verts,  // (V,3)
            int n)
{
    const int m = n - 1;
    int j = blockIdx.x * blockDim.x + threadIdx.x;
    int i = blockIdx.y;
    double val = 0.0;

    if (j < m) {
        // grid vertex ids
        int v00 = i * n + j;
        int v10 = v00 + n;
        int v01 = v00 + 1;
        int v11 = v10 + 1;

        int fT1 = i * m + j;
        int fT2 = m * m + fT1;

        // mesh vertex positions
        V3 p00 = ld3(verts + 3 * (size_t)v00);
        V3 p10 = ld3(verts + 3 * (size_t)v10);
        V3 p01 = ld3(verts + 3 * (size_t)v01);
        V3 p11 = ld3(verts + 3 * (size_t)v11);

        float aT1 = tri_area(p00, p10, p01);   // tri1(i,j): (v00,v10,v01)
        float aT2 = tri_area(p10, p11, p01);   // tri2(i,j): (v10,v11,v01)

        // transformed_prism rows of the two cell faces
        const float* q1 = tp + 9 * (size_t)fT1;
        const float* q2 = tp + 9 * (size_t)fT2;
        V3 t1_1 = ld3(q1 + 3), t1_2 = ld3(q1 + 6);
        V3 t2_0 = ld3(q2),     t2_1 = ld3(q2 + 3), t2_2 = ld3(q2 + 6);

        // vertex-id-indexed "normals" (matches reference's normals[edges[:,k]])
        V3 n10 = face_normal(tp + 9 * (size_t)v10);
        V3 n01 = face_normal(tp + 9 * (size_t)v01);
        V3 n11 = face_normal(tp + 9 * (size_t)v11);

        const float* r1 = rot + 9 * (size_t)fT1;
        const float* r2 = rot + 9 * (size_t)fT2;

        // ---- diagonal edge (v10, v01): tri1 has v10@1, v01@2; tri2 has v10@0, v01@2
        {
            V3 u = vsub(t1_1, t2_0);           // vertex v10
            V3 w = vsub(t1_2, t2_2);           // vertex v01
            V3 d = vsub(p10, p01);
            val += edge_term(u, w, n10, n01, r1, r2, vdot(d, d), aT1 + aT2);
        }

        // ---- horizontal edge (v10, v11): tri2(i,j) {v10@0,v11@1}, tri1(i+1,j) {v10@0,v11@2}
        if (i < m - 1) {
            int fD = fT1 + m;
            const float* qd = tp + 9 * (size_t)fD;
            V3 td_0 = ld3(qd), td_2 = ld3(qd + 6);
            V3 p20 = ld3(verts + 3 * (size_t)(v10 + n));       // (i+2, j)
            float aD = tri_area(p10, p20, p11);                 // tri1(i+1,j): (v10,v20,v11)
            V3 u = vsub(t2_0, td_0);           // vertex v10
            V3 w = vsub(t2_1, td_2);           // vertex v11
            V3 d = vsub(p10, p11);
            val += edge_term(u, w, n10, n11, r2, rot + 9 * (size_t)fD, vdot(d, d), aT2 + aD);
        }

        // ---- vertical edge (v11, v01): tri2(i,j) {v11@1,v01@2}, tri1(i,j+1) {v01@0,v11@1}
        if (j < m - 1) {
            int fR = fT1 + 1;
            const float* qr = tp + 9 * (size_t)fR;
            V3 tr_0 = ld3(qr), tr_1 = ld3(qr + 3);
            V3 p02 = ld3(verts + 3 * (size_t)(v01 + 1));       // (i, j+2)
            float aR = tri_area(p01, p11, p02);                 // tri1(i,j+1): (v01,v11,v02)
            V3 u = vsub(t2_1, tr_1);           // vertex v11
            V3 w = vsub(t2_2, tr_0);           // vertex v01
            V3 d = vsub(p11, p01);
            val += edge_term(u, w, n11, n01, r2, rot + 9 * (size_t)fR, vdot(d, d), aT2 + aR);
        }
    }

    // ---- block reduction in double, one atomic per block ----
    #pragma unroll
    for (int off = 16; off > 0; off >>= 1)
        val += __shfl_down_sync(0xFFFFFFFFu, val, off);

    __shared__ double sh[8];
    int lane = threadIdx.x & 31;
    int wid  = threadIdx.x >> 5;
    if (lane == 0) sh[wid] = val;
    __syncthreads();
    if (wid == 0) {
        val = (lane < (blockDim.x >> 5)) ? sh[lane] : 0.0;
        #pragma unroll
        for (int off = 4; off > 0; off >>= 1)
            val += __shfl_down_sync(0xFFFFFFFFu, val, off);
        if (lane == 0) atomicAdd(&g_sum, val);
    }
}

__global__ void k_fin(float* __restrict__ out) {
    out[0] = (float)g_sum;   // bs == 1
}

extern "C" void kernel_launch(void* const* d_in, const int* in_sizes, int n_in,
                              void* d_out, int out_size)
{
    const float* tp    = (const float*)d_in[0];   // (F,3,3)
    const float* rot   = (const float*)d_in[1];   // (F,3,3)
    const float* verts = (const float*)d_in[2];   // (1,V,3)

    int V = in_sizes[2] / 3;
    int n = (int)(sqrt((double)V) + 0.5);
    int m = n - 1;

    k_init<<<1, 1>>>();
    dim3 block(256, 1, 1);
    dim3 grid((m + 255) / 256, m, 1);
    k_cell<<<grid, block>>>(tp, rot, verts, n);
    k_fin<<<1, 1>>>((float*)d_out);
}